// round 5
// baseline (speedup 1.0000x reference)
#include <cuda_runtime.h>
#include <cstdint>

#define TT 16384
#define DD 2048
#define EE 64
#define KSEL 8
#define BR 64
#define DC 32
#define NIT (DD / DC)   // 64 stages

typedef unsigned long long ull;

// scratch (no allocations allowed): duplicated+transposed W, global accumulators
__device__ float g_wt[DD * 2 * EE];   // [2048][128]: g_wt[d*128 + 2e + {0,1}] = W[e][d]
__device__ float g_cnt[EE];
__device__ float g_pn[EE];

// ---------------------------------------------------------------------------
// Kernel A: zero accumulators + build duplicated/transposed W
// ---------------------------------------------------------------------------
__global__ void prep_kernel(const float* __restrict__ W) {
    int idx = blockIdx.x * blockDim.x + threadIdx.x;
    if (blockIdx.x == 0 && threadIdx.x < 2 * EE) {
        if (threadIdx.x < EE) g_cnt[threadIdx.x] = 0.f;
        else                  g_pn[threadIdx.x - EE] = 0.f;
    }
    if (idx < DD * EE) {
        int e = idx >> 11;          // idx = e*2048 + d  (coalesced read)
        int d = idx & (DD - 1);
        float v = W[idx];
        g_wt[d * 128 + 2 * e]     = v;
        g_wt[d * 128 + 2 * e + 1] = v;
    }
}

// ---------------------------------------------------------------------------
// packed fp32x2 FMA (FFMA2) — only reachable via PTX
// ---------------------------------------------------------------------------
__device__ __forceinline__ void ffma2(ull& c, ull a, ull b) {
    asm volatile("fma.rn.f32x2 %0, %1, %2, %0;" : "+l"(c) : "l"(a), "l"(b));
}

extern __shared__ float smem[];

// ---------------------------------------------------------------------------
// Kernel B: fused GEMM (fp32x2) + sigmoid + top-8 + gates + balance partials
//   grid = 256 blocks (64 rows each), 256 threads
//   dynamic smem 48KB: Xs[2][32][64] (16KB) + Ws[2][32][128] (32KB),
//   overlaid by L[64][68] in the epilogue.
// ---------------------------------------------------------------------------
__global__ void __launch_bounds__(256, 2) router_kernel(
    const float* __restrict__ x,
    const float* __restrict__ bias,
    float* __restrict__ out)
{
    float* Xs = smem;           // [2][DC][64], d-major per buffer
    float* Ws = smem + 4096;    // [2][DC][128]
    float* L  = smem;           // epilogue overlay: [64][68]

    __shared__ float bias_s[EE];
    __shared__ float cnt_s[EE];

    const int t  = threadIdx.x;
    const int tx = t & 15;      // expert group: experts 4*tx .. 4*tx+3
    const int ty = t >> 4;      // row group:    rows    4*ty .. 4*ty+3
    const int r0 = blockIdx.x * BR;

    if (t < EE) { bias_s[t] = bias[t]; cnt_s[t] = 0.f; }

    // ---- X global-load mapping: 64 rows x 32 d per stage, 2 float4 per thread
    const int xc = t & 7;       // float4 chunk within the 32-d stage (0..7)
    const int xr = t >> 3;      // row 0..31 (and +32)
    const float4* xptr0 = (const float4*)(x + (size_t)(r0 + xr)      * DD) + xc;
    const float4* xptr1 = (const float4*)(x + (size_t)(r0 + xr + 32) * DD) + xc;

    // ---- W cp.async mapping: 32 rows x 128 floats = 1024 float4, 4 per thread
    const int wc = t & 31;      // float4 column 0..31
    const int wd = t >> 5;      // d row 0..7 (strided by 8)
    const float4* wsrc = (const float4*)g_wt + wd * 32 + wc;

    ull acc[2][4];
    #pragma unroll
    for (int p = 0; p < 2; p++)
        #pragma unroll
        for (int e = 0; e < 4; e++) acc[p][e] = 0ULL;

    float4 rx0, rx1;

    // ---- prologue: stage 0
    rx0 = xptr0[0];
    rx1 = xptr1[0];
    {
        #pragma unroll
        for (int j = 0; j < 4; j++) {
            uint32_t sa = (uint32_t)__cvta_generic_to_shared(
                Ws + ((wd + 8 * j) * 128 + 4 * wc));
            asm volatile("cp.async.cg.shared.global [%0], [%1], 16;"
                         :: "r"(sa), "l"(wsrc + (size_t)(8 * j) * 32));
        }
        asm volatile("cp.async.commit_group;");
    }

    // ---- main pipelined loop
    for (int it = 0; it < NIT; it++) {
        const int b = it & 1;
        float* xb = Xs + b * 2048;

        // store this stage's X from registers (transposed to d-major)
        {
            float v0[4] = {rx0.x, rx0.y, rx0.z, rx0.w};
            float v1[4] = {rx1.x, rx1.y, rx1.z, rx1.w};
            #pragma unroll
            for (int k = 0; k < 4; k++) xb[(4 * xc + k) * 64 + xr]      = v0[k];
            #pragma unroll
            for (int k = 0; k < 4; k++) xb[(4 * xc + k) * 64 + xr + 32] = v1[k];
        }

        if (it + 1 < NIT) {
            // prefetch next X into registers, next W via cp.async
            rx0 = xptr0[(size_t)(it + 1) * 8];
            rx1 = xptr1[(size_t)(it + 1) * 8];
            float* dst = Ws + (b ^ 1) * 4096;
            const float4* src = wsrc + (size_t)(it + 1) * DC * 32;
            #pragma unroll
            for (int j = 0; j < 4; j++) {
                uint32_t sa = (uint32_t)__cvta_generic_to_shared(
                    dst + ((wd + 8 * j) * 128 + 4 * wc));
                asm volatile("cp.async.cg.shared.global [%0], [%1], 16;"
                             :: "r"(sa), "l"(src + (size_t)(8 * j) * 32));
            }
            asm volatile("cp.async.commit_group;");
            asm volatile("cp.async.wait_group 1;");
        } else {
            asm volatile("cp.async.wait_group 0;");
        }
        __syncthreads();

        const float* xcb = Xs + b * 2048;
        const float* wcb = Ws + b * 4096;
        #pragma unroll 8
        for (int d = 0; d < DC; d++) {
            ull xp0 = *(const ull*)(xcb + d * 64 + 4 * ty);       // (x_r0, x_r1)
            ull xp1 = *(const ull*)(xcb + d * 64 + 4 * ty + 2);   // (x_r2, x_r3)
            #pragma unroll
            for (int e = 0; e < 4; e++) {
                ull wv = *(const ull*)(wcb + d * 128 + 8 * tx + 2 * e); // (w_e, w_e)
                ffma2(acc[0][e], xp0, wv);
                ffma2(acc[1][e], xp1, wv);
            }
        }
        __syncthreads();
    }

    // ---- write logits into L[64][68] (overlay on the dead staging buffers)
    #pragma unroll
    for (int p = 0; p < 2; p++) {
        #pragma unroll
        for (int e = 0; e < 4; e++) {
            float2 f = *(float2*)&acc[p][e];
            int rr = 4 * ty + 2 * p;
            int ee = 4 * tx + e;
            L[rr * 68 + ee]       = f.x;
            L[(rr + 1) * 68 + ee] = f.y;
        }
    }
    __syncthreads();

    // ---- per-row: sigmoid, stable top-8, gate write, count partials
    if (t < BR) {
        const int r = t;
        float* Lr = L + r * 68;

        float ssum = 0.f;
        #pragma unroll
        for (int e = 0; e < EE; e++) {
            float sg = 1.f / (1.f + expf(-Lr[e]));
            Lr[e] = sg;                 // overwrite with affinity
            ssum += sg;
        }

        ull mask = 0ULL;
        float gsum = 0.f;
        float gv[KSEL];
        int   gi[KSEL];
        #pragma unroll
        for (int k = 0; k < KSEL; k++) {
            float best = -3.4e38f;
            int bi = 0;
            for (int e = 0; e < EE; e++) {
                if ((mask >> e) & 1ULL) continue;
                float v = Lr[e] + bias_s[e];
                if (v > best) { best = v; bi = e; }   // strict > => lowest index on ties
            }
            mask |= (1ULL << bi);
            gi[k] = bi;
            float a = Lr[bi];
            gv[k] = a;
            gsum += a;
            atomicAdd(&cnt_s[bi], 1.f);
        }

        const float inv = 1.f / (gsum + 1e-9f);
        const size_t rg = (size_t)r0 + r;
        #pragma unroll
        for (int k = 0; k < KSEL; k++) {
            out[rg * KSEL + k]                      = gv[k] * inv;
            out[(size_t)TT * KSEL + rg * KSEL + k]  = (float)gi[k];
        }

        const float pinv = 1.f / (ssum + 1e-9f);
        #pragma unroll
        for (int e = 0; e < EE; e++) Lr[e] *= pinv;   // affinity_norm for P
    }
    __syncthreads();

    // ---- per-expert partial sums -> global atomics (64 bins)
    {
        const int e = t & 63;
        const int seg = t >> 6;   // 0..3, 16 rows each
        float s = 0.f;
        #pragma unroll
        for (int r = seg * 16; r < seg * 16 + 16; r++) s += L[r * 68 + e];
        atomicAdd(&g_pn[e], s);
    }
    if (t < EE) atomicAdd(&g_cnt[t], cnt_s[t]);
}

// ---------------------------------------------------------------------------
// Kernel C: balance loss = alpha * sum_e (cnt_e * E/(K*T)) * (pn_e / T)
// ---------------------------------------------------------------------------
__global__ void finalize_kernel(float* __restrict__ out) {
    __shared__ float red[EE];
    const int e = threadIdx.x;
    red[e] = g_cnt[e] * g_pn[e];
    __syncthreads();
    if (e == 0) {
        float s = 0.f;
        for (int i = 0; i < EE; i++) s += red[i];
        double loss = (double)s * 1e-4 * 64.0 / (8.0 * 16384.0) / 16384.0;
        out[(size_t)2 * TT * KSEL] = (float)loss;
    }
}

// ---------------------------------------------------------------------------
extern "C" void kernel_launch(void* const* d_in, const int* in_sizes, int n_in,
                              void* d_out, int out_size) {
    const float* x    = (const float*)d_in[0];
    const float* W    = (const float*)d_in[1];
    const float* bias = (const float*)d_in[2];
    float* out = (float*)d_out;

    // Harden the launch: 49152 B dynamic + 512 B static smem — opt in explicitly
    // so the launch can never be rejected at the default 48KB dynamic ceiling.
    static bool attr_done = false;
    if (!attr_done) {
        cudaFuncSetAttribute(router_kernel,
                             cudaFuncAttributeMaxDynamicSharedMemorySize, 50176);
        attr_done = true;
    }

    prep_kernel<<<512, 256>>>(W);                            // 131072 threads
    router_kernel<<<TT / BR, 256, 49152>>>(x, bias, out);    // 256 blocks
    finalize_kernel<<<1, 64>>>(out);
}

// round 7
// speedup vs baseline: 3.9664x; 3.9664x over previous
#include <cuda_runtime.h>
#include <cstdint>

#define TT 16384
#define DD 2048
#define EE 64
#define KSEL 8
#define BR 128
#define DC 32
#define NIT (DD / DC)       // 64 stages
#define XSTR 34             // X smem row stride (floats): 8B-aligned, bank-staggered
#define WSTR 68             // W smem d-row stride (floats): 16B-aligned
#define XBUF (BR * XSTR)    // 4352 floats
#define WBUF (DC * WSTR)    // 2176 floats
// dynamic smem = 2*XBUF + 2*WBUF = 13056 floats = 52224 B
// epilogue overlay L[128][68] = 8704 floats fits inside.

typedef unsigned long long ull;

__device__ float g_wt[DD * EE];   // transposed W: g_wt[d*64 + e] = W[e][d]
__device__ float g_cnt[EE];
__device__ float g_pn[EE];

// ---------------------------------------------------------------------------
// Kernel A: zero accumulators + transpose W to d-major
// ---------------------------------------------------------------------------
__global__ void prep_kernel(const float* __restrict__ W) {
    int idx = blockIdx.x * blockDim.x + threadIdx.x;
    if (blockIdx.x == 0 && threadIdx.x < 2 * EE) {
        if (threadIdx.x < EE) g_cnt[threadIdx.x] = 0.f;
        else                  g_pn[threadIdx.x - EE] = 0.f;
    }
    if (idx < DD * EE) {
        int e = idx >> 11;            // coalesced read of W[e][d]
        int d = idx & (DD - 1);
        g_wt[d * EE + e] = W[idx];
    }
}

// packed fp32x2 FMA: each 32-bit lane is an independent sequential FFMA chain
__device__ __forceinline__ void ffma2(ull& c, ull a, ull b) {
    asm volatile("fma.rn.f32x2 %0, %1, %2, %0;" : "+l"(c) : "l"(a), "l"(b));
}
__device__ __forceinline__ ull dup32(uint32_t v) {
    ull r; asm("mov.b64 %0, {%1,%1};" : "=l"(r) : "r"(v)); return r;
}

extern __shared__ float smem[];

// ---------------------------------------------------------------------------
// Fused router: 128 blocks x 256 threads, 128 rows/block.
// Warp wi owns experts 8wi..8wi+7 (W loads warp-uniform -> broadcast).
// Lane l owns rows {l, l+32, l+64, l+96}.
// acc[i][p] = packed (sum_e, sum_{e+1}) for expert pair p of row i —
// each lane is a plain sequential-d FFMA chain (matches R5 numerics exactly).
// ---------------------------------------------------------------------------
__global__ void __launch_bounds__(256, 1) router_kernel(
    const float* __restrict__ x,
    const float* __restrict__ bias,
    float* __restrict__ out)
{
    float* Xs  = smem;                 // [2][XBUF]
    float* Wsm = smem + 2 * XBUF;      // [2][WBUF]
    float* L   = smem;                 // epilogue overlay [128][68]

    __shared__ float bias_s[EE];
    __shared__ float cnt_s[EE];

    const int t    = threadIdx.x;
    const int wi   = t >> 5;
    const int lane = t & 31;
    const int r0   = blockIdx.x * BR;

    if (t < EE) { bias_s[t] = bias[t]; cnt_s[t] = 0.f; }

    // ---- X staging via 8B cp.async: thread t -> row t>>1, 16 floats (t&1 half)
    const int xrow = t >> 1;
    const int xh   = t & 1;
    const float* xsrc = x + (size_t)(r0 + xrow) * DD + xh * 16;
    const uint32_t xdst = (uint32_t)__cvta_generic_to_shared(
        Xs + xrow * XSTR + xh * 16);
    const uint32_t XBUF_B = XBUF * 4;

    // ---- W staging via 16B cp.async: 512 chunks/stage, 2 per thread
    //      chunk c -> d = c>>4, q = c&15
    const int d1 = t >> 4,        q1 = t & 15;
    const int d2 = (t + 256) >> 4;  // q same
    const float* wsrc1 = g_wt + (size_t)d1 * EE + 4 * q1;
    const float* wsrc2 = g_wt + (size_t)d2 * EE + 4 * q1;
    const uint32_t wdst1 = (uint32_t)__cvta_generic_to_shared(
        Wsm + d1 * WSTR + 4 * q1);
    const uint32_t wdst2 = (uint32_t)__cvta_generic_to_shared(
        Wsm + d2 * WSTR + 4 * q1);
    const uint32_t WBUF_B = WBUF * 4;

    ull acc[4][4];
    #pragma unroll
    for (int i = 0; i < 4; i++)
        #pragma unroll
        for (int p = 0; p < 4; p++) acc[i][p] = 0ULL;

    // ---- prologue: stage 0
    {
        #pragma unroll
        for (int k = 0; k < 2; k++)
            asm volatile("cp.async.ca.shared.global [%0], [%1], 8;"
                         :: "r"(xdst + 8 * k), "l"(xsrc + 2 * k));
        #pragma unroll
        for (int k = 2; k < 8; k++)
            asm volatile("cp.async.ca.shared.global [%0], [%1], 8;"
                         :: "r"(xdst + 8 * k), "l"(xsrc + 2 * k));
        asm volatile("cp.async.cg.shared.global [%0], [%1], 16;" :: "r"(wdst1), "l"(wsrc1));
        asm volatile("cp.async.cg.shared.global [%0], [%1], 16;" :: "r"(wdst2), "l"(wsrc2));
        asm volatile("cp.async.commit_group;");
    }

    for (int s = 0; s < NIT; s++) {
        const int b = s & 1;

        if (s + 1 < NIT) {
            // prefetch stage s+1 into the other buffer
            const uint32_t xo = (b ^ 1) ? XBUF_B : 0u;
            const uint32_t wo = (b ^ 1) ? WBUF_B : 0u;
            const float* xs = xsrc + (size_t)(s + 1) * DC;
            const float* w1 = wsrc1 + (size_t)(s + 1) * DC * EE;
            const float* w2 = wsrc2 + (size_t)(s + 1) * DC * EE;
            #pragma unroll
            for (int k = 0; k < 8; k++)
                asm volatile("cp.async.ca.shared.global [%0], [%1], 8;"
                             :: "r"(xdst + xo + 8 * k), "l"(xs + 2 * k));
            asm volatile("cp.async.cg.shared.global [%0], [%1], 16;" :: "r"(wdst1 + wo), "l"(w1));
            asm volatile("cp.async.cg.shared.global [%0], [%1], 16;" :: "r"(wdst2 + wo), "l"(w2));
            asm volatile("cp.async.commit_group;");
            asm volatile("cp.async.wait_group 1;");
        } else {
            asm volatile("cp.async.wait_group 0;");
        }
        __syncthreads();

        // ---- compute stage s
        const float* xb = Xs + b * XBUF + lane * XSTR;
        const float* wb = Wsm + b * WBUF + 8 * wi;
        #pragma unroll 8
        for (int dl = 0; dl < DC; dl += 2) {
            // W for d=dl and d=dl+1: 4 expert-pairs each (warp-uniform)
            ulonglong2 wa0 = *(const ulonglong2*)(wb + dl * WSTR);
            ulonglong2 wa1 = *(const ulonglong2*)(wb + dl * WSTR + 4);
            ulonglong2 wb0 = *(const ulonglong2*)(wb + (dl + 1) * WSTR);
            ulonglong2 wb1 = *(const ulonglong2*)(wb + (dl + 1) * WSTR + 4);
            #pragma unroll
            for (int i = 0; i < 4; i++) {
                uint2 xv = *(const uint2*)(xb + i * (32 * XSTR) + dl);
                ull xa = dup32(xv.x);     // (x_d, x_d)
                ull xc = dup32(xv.y);     // (x_{d+1}, x_{d+1})
                ffma2(acc[i][0], xa, wa0.x);
                ffma2(acc[i][1], xa, wa0.y);
                ffma2(acc[i][2], xa, wa1.x);
                ffma2(acc[i][3], xa, wa1.y);
                ffma2(acc[i][0], xc, wb0.x);
                ffma2(acc[i][1], xc, wb0.y);
                ffma2(acc[i][2], xc, wb1.x);
                ffma2(acc[i][3], xc, wb1.y);
            }
        }
        __syncthreads();   // buffer b free before iter s+2 refills it
    }

    // ---- logits -> L[128][68]
    #pragma unroll
    for (int i = 0; i < 4; i++) {
        #pragma unroll
        for (int p = 0; p < 4; p++) {
            float2 f = *(float2*)&acc[i][p];
            const int rr = lane + 32 * i;
            const int ee = 8 * wi + 2 * p;
            L[rr * 68 + ee]     = f.x;
            L[rr * 68 + ee + 1] = f.y;
        }
    }
    __syncthreads();

    // ---- per-row: sigmoid, stable top-8 (strict > = lowest-index ties), gates
    if (t < BR) {
        float* Lr = L + t * 68;

        float ssum = 0.f;
        #pragma unroll
        for (int e = 0; e < EE; e++) {
            float sg = 1.f / (1.f + expf(-Lr[e]));
            Lr[e] = sg;
            ssum += sg;
        }

        ull mask = 0ULL;
        float gsum = 0.f;
        float gv[KSEL];
        int   gi[KSEL];
        #pragma unroll
        for (int k = 0; k < KSEL; k++) {
            float best = -3.4e38f;
            int bi = 0;
            for (int e = 0; e < EE; e++) {
                if ((mask >> e) & 1ULL) continue;
                float v = Lr[e] + bias_s[e];
                if (v > best) { best = v; bi = e; }
            }
            mask |= (1ULL << bi);
            gi[k] = bi;
            float a = Lr[bi];
            gv[k] = a;
            gsum += a;
            atomicAdd(&cnt_s[bi], 1.f);
        }

        const float inv = 1.f / (gsum + 1e-9f);
        const size_t rgl = (size_t)r0 + t;
        #pragma unroll
        for (int k = 0; k < KSEL; k++) {
            out[rgl * KSEL + k]                     = gv[k] * inv;
            out[(size_t)TT * KSEL + rgl * KSEL + k] = (float)gi[k];
        }

        const float pinv = 1.f / (ssum + 1e-9f);
        #pragma unroll
        for (int e = 0; e < EE; e++) Lr[e] *= pinv;   // affinity_norm for P
    }
    __syncthreads();

    // ---- per-expert partial sums of affinity_norm -> global atomics
    {
        const int e   = t & 63;
        const int seg = t >> 6;        // 4 segments x 32 rows
        float s = 0.f;
        #pragma unroll
        for (int r = seg * 32; r < seg * 32 + 32; r++) s += L[r * 68 + e];
        atomicAdd(&g_pn[e], s);
    }
    if (t < EE) atomicAdd(&g_cnt[t], cnt_s[t]);
}

// ---------------------------------------------------------------------------
// balance loss = alpha * sum_e (cnt_e * E/(K*T)) * (pn_e / T)
// ---------------------------------------------------------------------------
__global__ void finalize_kernel(float* __restrict__ out) {
    __shared__ float red[EE];
    const int e = threadIdx.x;
    red[e] = g_cnt[e] * g_pn[e];
    __syncthreads();
    if (e == 0) {
        float s = 0.f;
        for (int i = 0; i < EE; i++) s += red[i];
        double loss = (double)s * 1e-4 * 64.0 / (8.0 * 16384.0) / 16384.0;
        out[(size_t)2 * TT * KSEL] = (float)loss;
    }
}

// ---------------------------------------------------------------------------
extern "C" void kernel_launch(void* const* d_in, const int* in_sizes, int n_in,
                              void* d_out, int out_size) {
    const float* x    = (const float*)d_in[0];
    const float* W    = (const float*)d_in[1];
    const float* bias = (const float*)d_in[2];
    float* out = (float*)d_out;

    static bool attr_done = false;
    if (!attr_done) {
        cudaFuncSetAttribute(router_kernel,
                             cudaFuncAttributeMaxDynamicSharedMemorySize, 53248);
        attr_done = true;
    }

    prep_kernel<<<512, 256>>>(W);
    router_kernel<<<TT / BR, 256, 52224>>>(x, bias, out);
    finalize_kernel<<<1, 64>>>(out);
}